// round 15
// baseline (speedup 1.0000x reference)
#include <cuda_runtime.h>
#include <cuda_bf16.h>
#include <cstdint>

#define B_ 8192
#define D_ 2048
#define C_ 1000
#define EPS32 1.1920929e-7f

// ---------------- scratch (no allocations allowed) ----------------
__device__ __nv_bfloat16 g_z[B_ * (size_t)D_];   // z = feature + eps, bf16
__device__ __nv_bfloat16 g_w[C_ * (size_t)D_];   // cls_w, bf16 [C, D] K-major
__device__ float g_rowsum[B_];                   // per-row sum of raw probs
__device__ int   g_cnt_conv[64];                 // per-y-group conv complete
__device__ int   g_cnt_sum[64];                  // per-y-group rowsum complete

// ---------------- kernel 1: cls_w -> bf16 ; zero rowsum/cnts/loss -----------
__global__ void prep_w_kernel(const float4* __restrict__ w,
                              float* __restrict__ loss_ptr) {
    int i = blockIdx.x * blockDim.x + threadIdx.x;
    float4 a = w[i];
    __nv_bfloat162 lo = __floats2bfloat162_rn(a.x, a.y);
    __nv_bfloat162 hi = __floats2bfloat162_rn(a.z, a.w);
    union { __nv_bfloat162 h[2]; uint2 u; } pk;
    pk.h[0] = lo; pk.h[1] = hi;
    reinterpret_cast<uint2*>(g_w)[i] = pk.u;
    if (i < B_) g_rowsum[i] = 0.0f;
    if (i < 64) { g_cnt_conv[i] = 0; g_cnt_sum[i] = 0; }
    if (i == 0 && loss_ptr) *loss_ptr = 0.0f;
}

// ============================================================================
// Mega-kernel: [conv f+e -> z for own 16 rows] -> group flag -> GEMM mainloop
// (R5/R13 measured-best) -> bias + rowsum atomics -> group flag -> log + loss.
// CTA tile 128x128, BK=32, 4 stages, 128 thr = 4 warps (2m x 2n), warp 64x64,
// SW64 swizzle, occ 2. Grid (8, 64); 296 resident = 37 whole y-groups.
// ============================================================================
#define BM 128
#define BN 128
#define BK 32
#define STAGES 4
#define NIT (D_ / BK)               // 64
#define STAGE_BYTES 16384           // A: 128*64 = 8192, B: 8192
#define SMEM_TOTAL (STAGES * STAGE_BYTES)
#define NXT 8                       // CTAs per row group

#define SWZ64(o) ((o) ^ (((o) >> 3) & 0x30))

__device__ __forceinline__ uint32_t smem_u32(const void* p) {
    uint32_t a;
    asm("{ .reg .u64 t; cvta.to.shared.u64 t, %1; cvt.u32.u64 %0, t; }"
        : "=r"(a) : "l"(p));
    return a;
}
__device__ __forceinline__ void ldsm_x4(uint32_t r[4], uint32_t a) {
    asm volatile("ldmatrix.sync.aligned.m8n8.x4.shared.b16 {%0,%1,%2,%3}, [%4];"
                 : "=r"(r[0]), "=r"(r[1]), "=r"(r[2]), "=r"(r[3]) : "r"(a));
}
__device__ __forceinline__ void ldsm_x2(uint32_t r[2], uint32_t a) {
    asm volatile("ldmatrix.sync.aligned.m8n8.x2.shared.b16 {%0,%1}, [%2];"
                 : "=r"(r[0]), "=r"(r[1]) : "r"(a));
}
__device__ __forceinline__ void cpasync16(uint32_t dst, const void* src,
                                          uint32_t srcsz) {
    asm volatile("cp.async.cg.shared.global [%0], [%1], 16, %2;"
                 :: "r"(dst), "l"(src), "r"(srcsz));
}
__device__ __forceinline__ void mma16816(float c[4], const uint32_t a[4],
                                         uint32_t b0, uint32_t b1) {
    asm volatile(
        "mma.sync.aligned.m16n8k16.row.col.f32.bf16.bf16.f32 "
        "{%0,%1,%2,%3}, {%4,%5,%6,%7}, {%8,%9}, {%0,%1,%2,%3};\n"
        : "+f"(c[0]), "+f"(c[1]), "+f"(c[2]), "+f"(c[3])
        : "r"(a[0]), "r"(a[1]), "r"(a[2]), "r"(a[3]), "r"(b0), "r"(b1));
}

__global__ __launch_bounds__(128, 2) void gemm_kernel(
    const float4* __restrict__ f, const float4* __restrict__ e,
    const float* __restrict__ cls_b, const int* __restrict__ target,
    float* __restrict__ out, float* __restrict__ loss_ptr) {
    extern __shared__ char smem[];
    const uint32_t sb = smem_u32(smem);
    const int tid  = threadIdx.x;
    const int warp = tid >> 5;
    const int lane = tid & 31;
    const int wm   = warp >> 1;   // 0..1
    const int wn   = warp & 1;    // 0..1
    const int m0   = blockIdx.y * BM;
    const int n0   = blockIdx.x * BN;

    // ---- phase 0: convert own 16 A-rows (f + e -> bf16 z) ----
    {
        const size_t base4 = ((size_t)m0 + blockIdx.x * 16) * (D_ / 4);
#pragma unroll 4
        for (int j = 0; j < 64; j++) {
            const size_t idx = base4 + j * 128 + tid;   // 16 rows x 512 f4
            float4 a = __ldcs(&f[idx]);
            float4 b = __ldcs(&e[idx]);
            __nv_bfloat162 lo = __floats2bfloat162_rn(a.x + b.x, a.y + b.y);
            __nv_bfloat162 hi = __floats2bfloat162_rn(a.z + b.z, a.w + b.w);
            union { __nv_bfloat162 h[2]; uint2 u; } pk;
            pk.h[0] = lo; pk.h[1] = hi;
            reinterpret_cast<uint2*>(g_z)[idx] = pk.u;
        }
    }
    __threadfence();
    __syncthreads();
    if (tid == 0) {
        atomicAdd(&g_cnt_conv[blockIdx.y], 1);
        while (((volatile int*)g_cnt_conv)[blockIdx.y] < NXT) __nanosleep(100);
    }
    __syncthreads();
    __threadfence();   // acquire: z of whole group visible

    // ---- cp.async mapping: 4 A rows + 4 B rows per thread (16B chunks) ----
    const int r4 = tid >> 2;     // 0..31
    const int c4 = tid & 3;      // chunk 0..3
    const __nv_bfloat16* asrc[4];
    const __nv_bfloat16* bsrc[4];
    uint32_t adst[4], bdst[4], bsz[4];
#pragma unroll
    for (int i = 0; i < 4; i++) {
        const int row = r4 + i * 32;
        asrc[i] = &g_z[(size_t)(m0 + row) * D_ + c4 * 8];
        adst[i] = sb + SWZ64(row * 64 + c4 * 16);
        const int brow = n0 + row;
        bsz[i] = (brow < C_) ? 16u : 0u;
        bsrc[i] = &g_w[(size_t)((brow < C_) ? brow : (C_ - 1)) * D_ + c4 * 8];
        bdst[i] = sb + 8192 + SWZ64(row * 64 + c4 * 16);
    }

    // ---- ldmatrix per-lane offsets (within a stage) ----
    const int l15 = lane & 15;
    uint32_t aoff[2], boff[2];
#pragma unroll
    for (int kk = 0; kk < 2; kk++) {
        const int achunk = kk * 2 + (lane >> 4);
        aoff[kk] = SWZ64((wm * 64 + l15) * 64 + achunk * 16);
        const int bchunk = kk * 2 + ((l15 >> 3) & 1);
        boff[kk] = 8192 + SWZ64((wn * 64 + (l15 & 7)) * 64 + bchunk * 16);
    }

    float acc[4][8][4];
#pragma unroll
    for (int mi = 0; mi < 4; mi++)
#pragma unroll
        for (int ni = 0; ni < 8; ni++)
#pragma unroll
            for (int r = 0; r < 4; r++) acc[mi][ni][r] = 0.0f;

    // ---- prologue: 3 stages in flight ----
#pragma unroll
    for (int s = 0; s < STAGES - 1; s++) {
        const uint32_t so = s * STAGE_BYTES;
        const int k0 = s * BK;
#pragma unroll
        for (int i = 0; i < 4; i++) {
            cpasync16(adst[i] + so, asrc[i] + k0, 16u);
            cpasync16(bdst[i] + so, bsrc[i] + k0, bsz[i]);
        }
        asm volatile("cp.async.commit_group;" ::: "memory");
    }

    for (int it = 0; it < NIT; it++) {
        asm volatile("cp.async.wait_group 2;" ::: "memory");
        __syncthreads();

        if (it + STAGES - 1 < NIT) {
            const uint32_t so = ((it + STAGES - 1) & 3) * STAGE_BYTES;
            const int k0 = (it + STAGES - 1) * BK;
#pragma unroll
            for (int i = 0; i < 4; i++) {
                cpasync16(adst[i] + so, asrc[i] + k0, 16u);
                cpasync16(bdst[i] + so, bsrc[i] + k0, bsz[i]);
            }
        }
        asm volatile("cp.async.commit_group;" ::: "memory");

        const uint32_t base = sb + (it & 3) * STAGE_BYTES;
#pragma unroll
        for (int kk = 0; kk < 2; kk++) {
            uint32_t A[4][4];
#pragma unroll
            for (int mi = 0; mi < 4; mi++)
                ldsm_x4(A[mi], base + aoff[kk] + mi * 1024);  // +16 rows
            uint32_t Bf[8][2];
#pragma unroll
            for (int ni = 0; ni < 8; ni++)
                ldsm_x2(Bf[ni], base + boff[kk] + ni * 512);  // +8 n-rows
#pragma unroll
            for (int mi = 0; mi < 4; mi++)
#pragma unroll
                for (int ni = 0; ni < 8; ni++)
                    mma16816(acc[mi][ni], A[mi], Bf[ni][0], Bf[ni][1]);
        }
    }

    // ---- phase 1: add bias in place ; publish per-row partial sums ----
    const int g  = lane >> 2;
    const int tg = lane & 3;
#pragma unroll
    for (int mi = 0; mi < 4; mi++) {
        const int r0 = m0 + wm * 64 + mi * 16 + g;
        float ps0 = 0.0f, ps1 = 0.0f;
#pragma unroll
        for (int ni = 0; ni < 8; ni++) {
            const int col = n0 + wn * 64 + ni * 8 + tg * 2;
            if (col < C_) {   // C_ even -> col+1 valid too
                const float2 bb = *reinterpret_cast<const float2*>(cls_b + col);
                acc[mi][ni][0] += bb.x;
                acc[mi][ni][1] += bb.y;
                acc[mi][ni][2] += bb.x;
                acc[mi][ni][3] += bb.y;
                ps0 += acc[mi][ni][0] + acc[mi][ni][1];
                ps1 += acc[mi][ni][2] + acc[mi][ni][3];
            }
        }
        ps0 += __shfl_xor_sync(0xffffffffu, ps0, 1);
        ps0 += __shfl_xor_sync(0xffffffffu, ps0, 2);
        ps1 += __shfl_xor_sync(0xffffffffu, ps1, 1);
        ps1 += __shfl_xor_sync(0xffffffffu, ps1, 2);
        if (tg == 0) {
            atomicAdd(&g_rowsum[r0], ps0);
            atomicAdd(&g_rowsum[r0 + 8], ps1);
        }
    }

    // ---- cross-CTA handshake: wait for all 8 N-tiles of this row group ----
    __threadfence();
    __syncthreads();
    if (tid == 0) {
        atomicAdd(&g_cnt_sum[blockIdx.y], 1);
        while (((volatile int*)g_cnt_sum)[blockIdx.y] < NXT) __nanosleep(100);
    }
    __syncthreads();
    __threadfence();   // acquire: order rowsum reads after the flag

    // ---- phase 2: logits = log(clamp(acc/rowsum)) + loss ----
#pragma unroll
    for (int mi = 0; mi < 4; mi++) {
        const int r0 = m0 + wm * 64 + mi * 16 + g;
        const int r1 = r0 + 8;
        const float inv0 = __fdividef(1.0f, __ldcg(&g_rowsum[r0]));
        const float inv1 = __fdividef(1.0f, __ldcg(&g_rowsum[r1]));
        const int t0 = target[r0];
        const int t1 = target[r1];
#pragma unroll
        for (int ni = 0; ni < 8; ni++) {
            const int col = n0 + wn * 64 + ni * 8 + tg * 2;
            if (col < C_) {
                float p;
                float2 o0, o1;
                p = fminf(fmaxf(acc[mi][ni][0] * inv0, EPS32), 1.0f - EPS32);
                o0.x = __logf(p);
                p = fminf(fmaxf(acc[mi][ni][1] * inv0, EPS32), 1.0f - EPS32);
                o0.y = __logf(p);
                p = fminf(fmaxf(acc[mi][ni][2] * inv1, EPS32), 1.0f - EPS32);
                o1.x = __logf(p);
                p = fminf(fmaxf(acc[mi][ni][3] * inv1, EPS32), 1.0f - EPS32);
                o1.y = __logf(p);
                *reinterpret_cast<float2*>(out + (size_t)r0 * C_ + col) = o0;
                *reinterpret_cast<float2*>(out + (size_t)r1 * C_ + col) = o1;
                // loss = mean(gamma*rex + h3); gamma ~ 3.7e-44 makes gamma*rex
                // (~1e-40) vanish when added to h3 ~ 6.9 in fp32, so
                // loss == mean(-logits[b, target[b]]). Exactly one thread in
                // the grid matches each (row, target[row]) pair.
                if (loss_ptr) {
                    if (t0 == col)     atomicAdd(loss_ptr, -o0.x * (1.0f / (float)B_));
                    if (t0 == col + 1) atomicAdd(loss_ptr, -o0.y * (1.0f / (float)B_));
                    if (t1 == col)     atomicAdd(loss_ptr, -o1.x * (1.0f / (float)B_));
                    if (t1 == col + 1) atomicAdd(loss_ptr, -o1.y * (1.0f / (float)B_));
                }
            }
        }
    }
}

// ---------------- launch ----------------
extern "C" void kernel_launch(void* const* d_in, const int* in_sizes, int n_in,
                              void* d_out, int out_size) {
    const float* feature = (const float*)d_in[0];
    // d_in[1] = y_w, d_in[2] = y_b : unused (gamma*rex term vanishes in fp32)
    const float* cls_w   = (const float*)d_in[3];
    const float* cls_b   = (const float*)d_in[4];
    const float* eps     = (const float*)d_in[5];
    const int*   target  = (const int*)d_in[6];

    float* out = (float*)d_out;
    float* loss_ptr = (out_size >= B_ * C_ + 1) ? (out + (size_t)B_ * C_) : nullptr;

    cudaFuncSetAttribute(gemm_kernel,
                         cudaFuncAttributeMaxDynamicSharedMemorySize, SMEM_TOTAL);

    // 1) cls_w -> bf16 ; zero rowsum / counters / loss
    prep_w_kernel<<<(C_ * D_ / 4) / 256, 256>>>((const float4*)cls_w, loss_ptr);

    // 2) mega-kernel: conv(f+e->z) + GEMM + rowsum handshake + log + loss
    dim3 grid((C_ + BN - 1) / BN, B_ / BM);   // 8 x 64 = 512 CTAs
    gemm_kernel<<<grid, 128, SMEM_TOTAL>>>(
        (const float4*)feature, (const float4*)eps, cls_b, target, out, loss_ptr);
}

// round 16
// speedup vs baseline: 1.4319x; 1.4319x over previous
#include <cuda_runtime.h>
#include <cuda_bf16.h>
#include <cstdint>

#define B_ 8192
#define D_ 2048
#define C_ 1000
#define EPS32 1.1920929e-7f

// ---------------- scratch (no allocations allowed) ----------------
__device__ __nv_bfloat16 g_z[B_ * (size_t)D_];   // z = feature + eps, bf16
__device__ __nv_bfloat16 g_w[C_ * (size_t)D_];   // cls_w, bf16 [C, D] K-major
__device__ float g_rowsum[B_];                   // per-row sum of raw probs

#define ZBLOCKS (B_ * D_ / 4 / 256)              // 16384
#define WBLOCKS (C_ * D_ / 4 / 256)              // 2000

// ---------------- kernel 1: combined prep (z and w in one launch) -----------
// blocks [0, ZBLOCKS): z = bf16(f + e)  (one float4 per thread)
// blocks [ZBLOCKS, ZBLOCKS+WBLOCKS): w -> bf16 ; zero rowsum/loss
__global__ void prep_kernel(const float4* __restrict__ f,
                            const float4* __restrict__ e,
                            const float4* __restrict__ w,
                            float* __restrict__ loss_ptr) {
    if (blockIdx.x < ZBLOCKS) {
        const int i = blockIdx.x * 256 + threadIdx.x;
        float4 a = __ldcs(&f[i]);
        float4 b = __ldcs(&e[i]);
        __nv_bfloat162 lo = __floats2bfloat162_rn(a.x + b.x, a.y + b.y);
        __nv_bfloat162 hi = __floats2bfloat162_rn(a.z + b.z, a.w + b.w);
        union { __nv_bfloat162 h[2]; uint2 u; } pk;
        pk.h[0] = lo; pk.h[1] = hi;
        reinterpret_cast<uint2*>(g_z)[i] = pk.u;
    } else {
        const int i = (blockIdx.x - ZBLOCKS) * 256 + threadIdx.x;
        float4 a = __ldcs(&w[i]);
        __nv_bfloat162 lo = __floats2bfloat162_rn(a.x, a.y);
        __nv_bfloat162 hi = __floats2bfloat162_rn(a.z, a.w);
        union { __nv_bfloat162 h[2]; uint2 u; } pk;
        pk.h[0] = lo; pk.h[1] = hi;
        reinterpret_cast<uint2*>(g_w)[i] = pk.u;
        if (i < B_) g_rowsum[i] = 0.0f;
        if (i == 0 && loss_ptr) *loss_ptr = 0.0f;
    }
}

// ============================================================================
// GEMM raw = z @ w^T + cls_b : bf16 mma.sync m16n8k16 + ldmatrix + cp.async
// (R5 mainloop, measured best). CTA 128x128, BK=32, 4 stages. 128 threads =
// 4 warps (2m x 2n), warp tile 64x64. SMEM rows 64B, SW64 swizzled, occ 2.
// Produces per-row sums (atomicAdd into g_rowsum).
// ============================================================================
#define BM 128
#define BN 128
#define BK 32
#define STAGES 4
#define NIT (D_ / BK)               // 64
#define STAGE_BYTES 16384           // A: 128*64 = 8192, B: 8192
#define SMEM_TOTAL (STAGES * STAGE_BYTES)

#define SWZ64(o) ((o) ^ (((o) >> 3) & 0x30))

__device__ __forceinline__ uint32_t smem_u32(const void* p) {
    uint32_t a;
    asm("{ .reg .u64 t; cvta.to.shared.u64 t, %1; cvt.u32.u64 %0, t; }"
        : "=r"(a) : "l"(p));
    return a;
}
__device__ __forceinline__ void ldsm_x4(uint32_t r[4], uint32_t a) {
    asm volatile("ldmatrix.sync.aligned.m8n8.x4.shared.b16 {%0,%1,%2,%3}, [%4];"
                 : "=r"(r[0]), "=r"(r[1]), "=r"(r[2]), "=r"(r[3]) : "r"(a));
}
__device__ __forceinline__ void ldsm_x2(uint32_t r[2], uint32_t a) {
    asm volatile("ldmatrix.sync.aligned.m8n8.x2.shared.b16 {%0,%1}, [%2];"
                 : "=r"(r[0]), "=r"(r[1]) : "r"(a));
}
__device__ __forceinline__ void cpasync16(uint32_t dst, const void* src,
                                          uint32_t srcsz) {
    asm volatile("cp.async.cg.shared.global [%0], [%1], 16, %2;"
                 :: "r"(dst), "l"(src), "r"(srcsz));
}
__device__ __forceinline__ void mma16816(float c[4], const uint32_t a[4],
                                         uint32_t b0, uint32_t b1) {
    asm volatile(
        "mma.sync.aligned.m16n8k16.row.col.f32.bf16.bf16.f32 "
        "{%0,%1,%2,%3}, {%4,%5,%6,%7}, {%8,%9}, {%0,%1,%2,%3};\n"
        : "+f"(c[0]), "+f"(c[1]), "+f"(c[2]), "+f"(c[3])
        : "r"(a[0]), "r"(a[1]), "r"(a[2]), "r"(a[3]), "r"(b0), "r"(b1));
}

__global__ __launch_bounds__(128, 2) void gemm_kernel(
    const float* __restrict__ cls_b, float* __restrict__ raw) {
    extern __shared__ char smem[];
    const uint32_t sb = smem_u32(smem);
    const int tid  = threadIdx.x;
    const int warp = tid >> 5;
    const int lane = tid & 31;
    const int wm   = warp >> 1;   // 0..1
    const int wn   = warp & 1;    // 0..1
    const int m0   = blockIdx.y * BM;
    const int n0   = blockIdx.x * BN;

    // ---- cp.async mapping: 4 A rows + 4 B rows per thread (16B chunks) ----
    const int r4 = tid >> 2;     // 0..31
    const int c4 = tid & 3;      // chunk 0..3
    const __nv_bfloat16* asrc[4];
    const __nv_bfloat16* bsrc[4];
    uint32_t adst[4], bdst[4], bsz[4];
#pragma unroll
    for (int i = 0; i < 4; i++) {
        const int row = r4 + i * 32;
        asrc[i] = &g_z[(size_t)(m0 + row) * D_ + c4 * 8];
        adst[i] = sb + SWZ64(row * 64 + c4 * 16);
        const int brow = n0 + row;
        bsz[i] = (brow < C_) ? 16u : 0u;
        bsrc[i] = &g_w[(size_t)((brow < C_) ? brow : (C_ - 1)) * D_ + c4 * 8];
        bdst[i] = sb + 8192 + SWZ64(row * 64 + c4 * 16);
    }

    // ---- ldmatrix per-lane offsets (within a stage) ----
    const int l15 = lane & 15;
    uint32_t aoff[2], boff[2];
#pragma unroll
    for (int kk = 0; kk < 2; kk++) {
        const int achunk = kk * 2 + (lane >> 4);
        aoff[kk] = SWZ64((wm * 64 + l15) * 64 + achunk * 16);
        const int bchunk = kk * 2 + ((l15 >> 3) & 1);
        boff[kk] = 8192 + SWZ64((wn * 64 + (l15 & 7)) * 64 + bchunk * 16);
    }

    float acc[4][8][4];
#pragma unroll
    for (int mi = 0; mi < 4; mi++)
#pragma unroll
        for (int ni = 0; ni < 8; ni++)
#pragma unroll
            for (int r = 0; r < 4; r++) acc[mi][ni][r] = 0.0f;

    // ---- prologue: 3 stages in flight ----
#pragma unroll
    for (int s = 0; s < STAGES - 1; s++) {
        const uint32_t so = s * STAGE_BYTES;
        const int k0 = s * BK;
#pragma unroll
        for (int i = 0; i < 4; i++) {
            cpasync16(adst[i] + so, asrc[i] + k0, 16u);
            cpasync16(bdst[i] + so, bsrc[i] + k0, bsz[i]);
        }
        asm volatile("cp.async.commit_group;" ::: "memory");
    }

    for (int it = 0; it < NIT; it++) {
        asm volatile("cp.async.wait_group 2;" ::: "memory");
        __syncthreads();

        if (it + STAGES - 1 < NIT) {
            const uint32_t so = ((it + STAGES - 1) & 3) * STAGE_BYTES;
            const int k0 = (it + STAGES - 1) * BK;
#pragma unroll
            for (int i = 0; i < 4; i++) {
                cpasync16(adst[i] + so, asrc[i] + k0, 16u);
                cpasync16(bdst[i] + so, bsrc[i] + k0, bsz[i]);
            }
        }
        asm volatile("cp.async.commit_group;" ::: "memory");

        const uint32_t base = sb + (it & 3) * STAGE_BYTES;
#pragma unroll
        for (int kk = 0; kk < 2; kk++) {
            uint32_t A[4][4];
#pragma unroll
            for (int mi = 0; mi < 4; mi++)
                ldsm_x4(A[mi], base + aoff[kk] + mi * 1024);  // +16 rows
            uint32_t Bf[8][2];
#pragma unroll
            for (int ni = 0; ni < 8; ni++)
                ldsm_x2(Bf[ni], base + boff[kk] + ni * 512);  // +8 n-rows
#pragma unroll
            for (int mi = 0; mi < 4; mi++)
#pragma unroll
                for (int ni = 0; ni < 8; ni++)
                    mma16816(acc[mi][ni], A[mi], Bf[ni][0], Bf[ni][1]);
        }
    }

    // ---- store: raw = acc + cls_b ; accumulate per-row sums ----
    const int g  = lane >> 2;
    const int tg = lane & 3;
#pragma unroll
    for (int mi = 0; mi < 4; mi++) {
        const int r0 = m0 + wm * 64 + mi * 16 + g;
        float ps0 = 0.0f, ps1 = 0.0f;
#pragma unroll
        for (int ni = 0; ni < 8; ni++) {
            const int col = n0 + wn * 64 + ni * 8 + tg * 2;
            if (col < C_) {   // C_ even -> col+1 valid too
                const float2 bb = *reinterpret_cast<const float2*>(cls_b + col);
                float2 o0, o1;
                o0.x = acc[mi][ni][0] + bb.x;
                o0.y = acc[mi][ni][1] + bb.y;
                o1.x = acc[mi][ni][2] + bb.x;
                o1.y = acc[mi][ni][3] + bb.y;
                *reinterpret_cast<float2*>(raw + (size_t)r0 * C_ + col) = o0;
                *reinterpret_cast<float2*>(raw + (size_t)(r0 + 8) * C_ + col) = o1;
                ps0 += o0.x + o0.y;
                ps1 += o1.x + o1.y;
            }
        }
        // reduce across the 4 tg lanes (same g)
        ps0 += __shfl_xor_sync(0xffffffffu, ps0, 1);
        ps0 += __shfl_xor_sync(0xffffffffu, ps0, 2);
        ps1 += __shfl_xor_sync(0xffffffffu, ps1, 1);
        ps1 += __shfl_xor_sync(0xffffffffu, ps1, 2);
        if (tg == 0) {
            atomicAdd(&g_rowsum[r0], ps0);
            atomicAdd(&g_rowsum[r0 + 8], ps1);
        }
    }
}

// ---------------- kernel 3: streaming normalize/log + loss ------------------
// 4 rows per block (R5 config, best measured 18.3us); rowsum precomputed
__global__ __launch_bounds__(256) void epilogue_kernel(
    float* __restrict__ out, const int* __restrict__ target,
    float* __restrict__ loss_ptr) {
    const int row0 = blockIdx.x * 4;
    const int tid  = threadIdx.x;
    if (tid >= 250) return;

    // issue all independent loads first (MLP)
    float4 v[4];
    float  sum[4];
#pragma unroll
    for (int j = 0; j < 4; j++) {
        v[j] = *reinterpret_cast<const float4*>(
            out + (size_t)(row0 + j) * C_ + tid * 4);
        sum[j] = g_rowsum[row0 + j];
    }

#pragma unroll
    for (int j = 0; j < 4; j++) {
        const int row = row0 + j;
        const float inv = __fdividef(1.0f, sum[j]);
        float4 lg;
        float p;
        p = fminf(fmaxf(v[j].x * inv, EPS32), 1.0f - EPS32); lg.x = __logf(p);
        p = fminf(fmaxf(v[j].y * inv, EPS32), 1.0f - EPS32); lg.y = __logf(p);
        p = fminf(fmaxf(v[j].z * inv, EPS32), 1.0f - EPS32); lg.z = __logf(p);
        p = fminf(fmaxf(v[j].w * inv, EPS32), 1.0f - EPS32); lg.w = __logf(p);
        *reinterpret_cast<float4*>(out + (size_t)row * C_ + tid * 4) = lg;

        if (loss_ptr) {
            const int tgt  = target[row];
            const int base = tid * 4;
            if (tgt >= base && tgt < base + 4) {
                const float l = (tgt == base) ? lg.x : (tgt == base + 1) ? lg.y
                              : (tgt == base + 2) ? lg.z : lg.w;
                // loss = mean(gamma*rex + h3); gamma ~ 3.7e-44 makes gamma*rex
                // (~1e-40) vanish when added to h3 ~ 6.9 in fp32, so
                // loss == mean(-logits[b, target[b]]).
                atomicAdd(loss_ptr, -l * (1.0f / (float)B_));
            }
        }
    }
}

// ---------------- launch ----------------
extern "C" void kernel_launch(void* const* d_in, const int* in_sizes, int n_in,
                              void* d_out, int out_size) {
    const float* feature = (const float*)d_in[0];
    // d_in[1] = y_w, d_in[2] = y_b : unused (gamma*rex term vanishes in fp32)
    const float* cls_w   = (const float*)d_in[3];
    const float* cls_b   = (const float*)d_in[4];
    const float* eps     = (const float*)d_in[5];
    const int*   target  = (const int*)d_in[6];

    float* out = (float*)d_out;
    float* loss_ptr = (out_size >= B_ * C_ + 1) ? (out + (size_t)B_ * C_) : nullptr;

    cudaFuncSetAttribute(gemm_kernel,
                         cudaFuncAttributeMaxDynamicSharedMemorySize, SMEM_TOTAL);

    // 1) combined prep: z = bf16(f+e), w -> bf16, zero rowsum/loss
    prep_kernel<<<ZBLOCKS + WBLOCKS, 256>>>(
        (const float4*)feature, (const float4*)eps, (const float4*)cls_w,
        loss_ptr);

    // 2) raw = z @ cls_w^T + cls_b (into d_out) + per-row sums
    dim3 grid((C_ + BN - 1) / BN, B_ / BM);   // 8 x 64 = 512 CTAs
    gemm_kernel<<<grid, 128, SMEM_TOTAL>>>(cls_b, out);

    // 3) logits = log(clamp(raw / rowsum)), loss = mean(-logits[b, target])
    epilogue_kernel<<<B_ / 4, 256>>>(out, target, loss_ptr);
}